// round 16
// baseline (speedup 1.0000x reference)
#include <cuda_runtime.h>
#include <cuda_fp16.h>
#include <cstdint>

#define NNODES 65536
#define NC 256

typedef unsigned long long u64;

// Persistent scratch (no allocations allowed)
__device__ float g_bufA[NNODES * NC];       // agg (fp32 atomics, PERMUTED channel order)
__device__ float g_bufB[NNODES * NC];       // conv_out -> later g (linear channels)
__device__ uint32_t g_xh[NNODES * 128];     // xt packed half (permuted)
__device__ uint32_t g_wth[9 * 256 * 128];   // conv weights packed half [tap][co][...]
__device__ uint32_t g_nodesh[NNODES * 128]; // nodes packed half (permuted)
__device__ uint32_t g_aggh[NNODES * 128];   // agg packed half (permuted)
__device__ uint32_t g_wch[16 * 256 * 16];   // [wrel|wroot] packed half [chunk][co][...]
__device__ float g_stats[1024];
__device__ float g_coef[1024];
__device__ int   g_is32;

__device__ __forceinline__ uint32_t h2u(float x, float y) {
    __half2 h = __floats2half2_rn(x, y);
    return *(uint32_t*)&h;
}
// permuted pack of 16 consecutive channels: q[2j]={f2j,f2j+1}, q[2j+1]={f8+2j,f9+2j}
__device__ __forceinline__ void pack16(uint32_t* q, const float* f) {
    #pragma unroll
    for (int j = 0; j < 4; j++) {
        q[2 * j]     = h2u(f[2 * j], f[2 * j + 1]);
        q[2 * j + 1] = h2u(f[8 + 2 * j], f[9 + 2 * j]);
    }
}
__device__ __forceinline__ void mma16(float* c, uint2 alo, uint2 ahi, uint2 b) {
    asm volatile(
        "mma.sync.aligned.m16n8k16.row.col.f32.f16.f16.f32 "
        "{%0,%1,%2,%3}, {%4,%5,%6,%7}, {%8,%9}, {%0,%1,%2,%3};"
        : "+f"(c[0]), "+f"(c[1]), "+f"(c[2]), "+f"(c[3])
        : "r"(alo.x), "r"(ahi.x), "r"(alo.y), "r"(ahi.y), "r"(b.x), "r"(b.y));
}

// ---------------- transpose x: NCHW -> packed half node-major ----------------
__global__ void k_transpose_x(const float* __restrict__ x) {
    __shared__ float tile[256 * 33];
    int bh = blockIdx.x;
    int b = bh >> 5, h = bh & 31;
    for (int i = threadIdx.x; i < 8192; i += 256) {
        int c = i >> 5, w = i & 31;
        tile[c * 33 + w] = x[((b * NC + c) * 32 + h) * 32 + w];
    }
    __syncthreads();
    int nb = bh * 32;
    for (int i = threadIdx.x; i < 512; i += 256) {
        int w = i >> 4, g = i & 15, kc = g >> 1, hh = g & 1;
        float f[16];
        #pragma unroll
        for (int j = 0; j < 16; j++) f[j] = tile[(kc * 32 + hh * 16 + j) * 33 + w];
        uint32_t q[8];
        pack16(q, f);
        uint4* dst = (uint4*)&g_xh[(nb + w) * 128 + kc * 16 + hh * 8];
        dst[0] = ((uint4*)q)[0];
        dst[1] = ((uint4*)q)[1];
    }
}

// ---------------- weight prep: pack conv & graph weights + zero stats --------
__global__ void k_prep(const float* __restrict__ cw,
                       const float* __restrict__ wrel,
                       const float* __restrict__ wroot) {
    int i = blockIdx.x * 256 + threadIdx.x;
    if (i < 36864) {   // conv: tap(9) x co(256) x kc(8) x h(2)
        int h = i & 1, kc = (i >> 1) & 7, co = (i >> 4) & 255, tap = i >> 12;
        float f[16];
        #pragma unroll
        for (int j = 0; j < 16; j++)
            f[j] = cw[(co * 256 + kc * 32 + h * 16 + j) * 9 + tap];
        uint32_t q[8];
        pack16(q, f);
        uint4* dst = (uint4*)&g_wth[(tap * 256 + co) * 128 + kc * 16 + h * 8];
        dst[0] = ((uint4*)q)[0];
        dst[1] = ((uint4*)q)[1];
    } else if (i < 45056) {   // graph: chunk(16) x co(256) x h(2)
        int t = i - 36864;
        int h = t & 1, co = (t >> 1) & 255, chc = t >> 9;
        const float* src = (chc < 8) ? wrel : wroot;
        float f[16];
        #pragma unroll
        for (int j = 0; j < 16; j++)
            f[j] = src[co * 256 + (chc & 7) * 32 + h * 16 + j];
        uint32_t q[8];
        pack16(q, f);
        uint4* dst = (uint4*)&g_wch[(chc * 256 + co) * 16 + h * 8];
        dst[0] = ((uint4*)q)[0];
        dst[1] = ((uint4*)q)[1];
    }
    if (blockIdx.x == 0) {
        for (int j = threadIdx.x; j < 1024; j += 256) g_stats[j] = 0.f;
    }
}

// ---------------- edge dtype detection ----------------
__global__ void k_detect(const int* __restrict__ ei32) {
    __shared__ int any;
    if (threadIdx.x == 0) any = 0;
    __syncthreads();
    int a = 0;
    for (int j = threadIdx.x; j < 8192; j += 256) a |= ei32[2 * j + 1];
    if (a) atomicOr(&any, 1);
    __syncthreads();
    if (threadIdx.x == 0) g_is32 = (any != 0) ? 1 : 0;
}

#define MMA_STEP(SBUF, S)                                                     \
    do {                                                                      \
        uint2 alo[4], ahi[4], bv[4];                                          \
        _Pragma("unroll")                                                     \
        for (int mt = 0; mt < 4; mt++) {                                      \
            int row = wm0 + mt * 16 + gA;                                     \
            alo[mt] = *(const uint2*)&As[SBUF][row * 24 + (S) * 8 + 2 * cA];  \
            ahi[mt] = *(const uint2*)&As[SBUF][(row + 8) * 24 + (S) * 8 + 2 * cA]; \
        }                                                                     \
        _Pragma("unroll")                                                     \
        for (int nt = 0; nt < 4; nt++)                                        \
            bv[nt] = *(const uint2*)&Bs[SBUF][(wn0 + nt * 8 + gA) * 24 + (S) * 8 + 2 * cA]; \
        _Pragma("unroll")                                                     \
        for (int mt = 0; mt < 4; mt++)                                        \
            _Pragma("unroll")                                                 \
            for (int nt = 0; nt < 4; nt++)                                    \
                mma16(c[mt][nt], alo[mt], ahi[mt], bv[nt]);                   \
    } while (0)

// epilogue + fused BN stats (sum/sumsq per column -> global atomics)
#define EPILOGUE(BIASP, SO)                                                   \
    do {                                                                      \
        float s8[8] = {}, q8[8] = {};                                         \
        _Pragma("unroll")                                                     \
        for (int mt = 0; mt < 4; mt++) {                                      \
            _Pragma("unroll")                                                 \
            for (int nt = 0; nt < 4; nt++) {                                  \
                int row = mbase + wm0 + mt * 16 + gA;                         \
                int col = nbase + wn0 + nt * 8 + 2 * cA;                      \
                float b0 = BIASP[col], b1 = BIASP[col + 1];                   \
                float v0 = c[mt][nt][0] + b0, v1 = c[mt][nt][1] + b1;         \
                float v2 = c[mt][nt][2] + b0, v3 = c[mt][nt][3] + b1;         \
                *(float2*)&g_bufB[row * NC + col] = make_float2(v0, v1);      \
                *(float2*)&g_bufB[(row + 8) * NC + col] = make_float2(v2, v3);\
                s8[nt * 2] += v0 + v2;     q8[nt * 2] += v0 * v0 + v2 * v2;   \
                s8[nt * 2 + 1] += v1 + v3; q8[nt * 2 + 1] += v1 * v1 + v3 * v3;\
            }                                                                 \
        }                                                                     \
        _Pragma("unroll")                                                     \
        for (int nt = 0; nt < 4; nt++) {                                      \
            int col = nbase + wn0 + nt * 8 + 2 * cA;                          \
            atomicAdd(&g_stats[(SO) + col], s8[nt * 2]);                      \
            atomicAdd(&g_stats[(SO) + 256 + col], q8[nt * 2]);                \
            atomicAdd(&g_stats[(SO) + col + 1], s8[nt * 2 + 1]);              \
            atomicAdd(&g_stats[(SO) + 256 + col + 1], q8[nt * 2 + 1]);        \
        }                                                                     \
    } while (0)

// ---------------- conv 3x3: implicit GEMM, fp16 m16n8k16 (R13 config) ------
__global__ __launch_bounds__(256, 2) void k_conv(const float* __restrict__ bias) {
    __shared__ __align__(16) uint32_t As[2][128 * 24];
    __shared__ __align__(16) uint32_t Bs[2][128 * 24];
    int tid = threadIdx.x;
    int wid = tid >> 5, lane = tid & 31;
    int mbase = blockIdx.x * 128, nbase = blockIdx.y * 128;
    int wm0 = (wid >> 2) * 64, wn0 = (wid & 3) * 32;
    int gA = lane >> 2, cA = lane & 3;
    int r = tid >> 1, h = tid & 1;
    float c[4][4][4] = {};
    uint4 z4 = make_uint4(0, 0, 0, 0);

    {
        int node = mbase + r;
        int hh = ((node >> 5) & 31) - 1, ww = (node & 31) - 1;
        bool ok = ((unsigned)hh < 32u) && ((unsigned)ww < 32u);
        const uint4* ap = (const uint4*)&g_xh[(node - 33) * 128 + h * 8];
        const uint4* bp = (const uint4*)&g_wth[(nbase + r) * 128 + h * 8];
        uint32_t* qa = &As[0][r * 24 + h * 8];
        uint32_t* qb = &Bs[0][r * 24 + h * 8];
        *(uint4*)qa = ok ? ap[0] : z4;
        *(uint4*)(qa + 4) = ok ? ap[1] : z4;
        *(uint4*)qb = bp[0];
        *(uint4*)(qb + 4) = bp[1];
    }
    __syncthreads();

    for (int ch = 0; ch < 72; ch++) {
        int cur = ch & 1, nxt = cur ^ 1;
        bool has = (ch + 1 < 72);
        uint4 pa0, pa1, pb0, pb1;
        if (has) {
            int c1 = ch + 1;
            int tap = c1 >> 3, kc = c1 & 7;
            int dy = tap / 3 - 1, dx = tap % 3 - 1;
            int node = mbase + r;
            int hh = ((node >> 5) & 31) + dy, ww = (node & 31) + dx;
            bool ok = ((unsigned)hh < 32u) && ((unsigned)ww < 32u);
            const uint4* ap = (const uint4*)&g_xh[(node + dy * 32 + dx) * 128 + kc * 16 + h * 8];
            const uint4* bp = (const uint4*)&g_wth[(tap * 256 + nbase + r) * 128 + kc * 16 + h * 8];
            pa0 = ok ? ap[0] : z4;
            pa1 = ok ? ap[1] : z4;
            pb0 = bp[0];
            pb1 = bp[1];
        }
        MMA_STEP(cur, 0);
        if (has) {
            uint32_t* qa = &As[nxt][r * 24 + h * 8];
            uint32_t* qb = &Bs[nxt][r * 24 + h * 8];
            *(uint4*)qa = pa0;
            *(uint4*)(qa + 4) = pa1;
            *(uint4*)qb = pb0;
            *(uint4*)(qb + 4) = pb1;
        }
        MMA_STEP(cur, 1);
        __syncthreads();
    }
    EPILOGUE(bias, 0);
}

__global__ void k_coef(int so, const float* __restrict__ gamma,
                       const float* __restrict__ beta, int co) {
    int c = threadIdx.x;
    float mean = g_stats[so + c] * (1.f / NNODES);
    float var  = g_stats[so + 256 + c] * (1.f / NNODES) - mean * mean;
    float sc = gamma[c] * rsqrtf(var + 1e-5f);
    g_coef[co + c] = sc;
    g_coef[co + 256 + c] = beta[c] - mean * sc;
}

// ---------------- bn2d+relu -> packed half nodes ; zero agg -----------------
__global__ void k_bnrelu_zero() {
    int i = blockIdx.x * 256 + threadIdx.x;   // 1048576 items
    int node = i >> 4, g = i & 15;
    int base = node * NC + g * 16;
    float f[16];
    float4 zz = make_float4(0.f, 0.f, 0.f, 0.f);
    #pragma unroll
    for (int j4 = 0; j4 < 4; j4++) {
        float4 v  = *(const float4*)&g_bufB[base + j4 * 4];
        float4 sc = *(const float4*)&g_coef[g * 16 + j4 * 4];
        float4 sh = *(const float4*)&g_coef[256 + g * 16 + j4 * 4];
        v.x = fmaxf(fmaf(v.x, sc.x, sh.x), 0.f);
        v.y = fmaxf(fmaf(v.y, sc.y, sh.y), 0.f);
        v.z = fmaxf(fmaf(v.z, sc.z, sh.z), 0.f);
        v.w = fmaxf(fmaf(v.w, sc.w, sh.w), 0.f);
        *(float4*)&g_bufA[base + j4 * 4] = zz;
        f[j4 * 4 + 0] = v.x; f[j4 * 4 + 1] = v.y;
        f[j4 * 4 + 2] = v.z; f[j4 * 4 + 3] = v.w;
    }
    uint32_t q[8];
    pack16(q, f);
    uint4* dst = (uint4*)&g_nodesh[node * 128 + g * 8];
    dst[0] = ((uint4*)q)[0];
    dst[1] = ((uint4*)q)[1];
}

// ---------------- edge scatter-add (half read, fp32 RED, permuted layout) ---
__global__ void k_scatter(const void* __restrict__ ei, int E) {
    int e = blockIdx.x * 8 + (threadIdx.x >> 5);
    if (e >= E) return;
    int lane = threadIdx.x & 31;
    int src, dst;
    if (g_is32) {
        const int* p = (const int*)ei;
        src = p[e]; dst = p[E + e];
    } else {
        const long long* p = (const long long*)ei;
        src = (int)p[e]; dst = (int)p[E + e];
    }
    uint4 v = ((const uint4*)&g_nodesh[src * 128])[lane];
    float2 f0 = __half22float2(*(__half2*)&v.x);
    float2 f1 = __half22float2(*(__half2*)&v.y);
    float2 f2 = __half22float2(*(__half2*)&v.z);
    float2 f3 = __half22float2(*(__half2*)&v.w);
    float* dp = &g_bufA[dst * NC + lane * 8];
    asm volatile("red.global.add.v4.f32 [%0], {%1,%2,%3,%4};"
                 :: "l"(dp), "f"(f0.x), "f"(f0.y), "f"(f1.x), "f"(f1.y) : "memory");
    asm volatile("red.global.add.v4.f32 [%0], {%1,%2,%3,%4};"
                 :: "l"(dp + 4), "f"(f2.x), "f"(f2.y), "f"(f3.x), "f"(f3.y) : "memory");
}

// ---------------- pack agg (already permuted) fp32 -> half ------------------
__global__ void k_cvt_agg() {
    int i = blockIdx.x * 256 + threadIdx.x;
    int node = i >> 4, g = i & 15;
    const float* f = &g_bufA[node * NC + g * 16];
    uint32_t q[8];
    #pragma unroll
    for (int j = 0; j < 8; j++) q[j] = h2u(f[2 * j], f[2 * j + 1]);
    uint4* dst = (uint4*)&g_aggh[node * 128 + g * 8];
    dst[0] = ((uint4*)q)[0];
    dst[1] = ((uint4*)q)[1];
}

// ---------------- graph GEMM (R13 config) -----------------------------------
__global__ __launch_bounds__(256, 2) void k_gemm(const float* __restrict__ brel) {
    __shared__ __align__(16) uint32_t As[2][128 * 24];
    __shared__ __align__(16) uint32_t Bs[2][128 * 24];
    int tid = threadIdx.x;
    int wid = tid >> 5, lane = tid & 31;
    int mbase = blockIdx.x * 128, nbase = blockIdx.y * 128;
    int wm0 = (wid >> 2) * 64, wn0 = (wid & 3) * 32;
    int gA = lane >> 2, cA = lane & 3;
    int r = tid >> 1, h = tid & 1;
    float c[4][4][4] = {};

    {
        const uint4* ap = (const uint4*)&g_aggh[(mbase + r) * 128 + h * 8];
        const uint4* bp = (const uint4*)&g_wch[(nbase + r) * 16 + h * 8];
        uint32_t* qa = &As[0][r * 24 + h * 8];
        uint32_t* qb = &Bs[0][r * 24 + h * 8];
        *(uint4*)qa = ap[0];
        *(uint4*)(qa + 4) = ap[1];
        *(uint4*)qb = bp[0];
        *(uint4*)(qb + 4) = bp[1];
    }
    __syncthreads();

    for (int ch = 0; ch < 16; ch++) {
        int cur = ch & 1, nxt = cur ^ 1;
        bool has = (ch + 1 < 16);
        uint4 pa0, pa1, pb0, pb1;
        if (has) {
            int c1 = ch + 1;
            const uint32_t* ab = (c1 < 8) ? g_aggh : g_nodesh;
            int kc = c1 & 7;
            const uint4* ap = (const uint4*)&ab[(mbase + r) * 128 + kc * 16 + h * 8];
            const uint4* bp = (const uint4*)&g_wch[(c1 * 256 + nbase + r) * 16 + h * 8];
            pa0 = ap[0]; pa1 = ap[1];
            pb0 = bp[0]; pb1 = bp[1];
        }
        MMA_STEP(cur, 0);
        if (has) {
            uint32_t* qa = &As[nxt][r * 24 + h * 8];
            uint32_t* qb = &Bs[nxt][r * 24 + h * 8];
            *(uint4*)qa = pa0;
            *(uint4*)(qa + 4) = pa1;
            *(uint4*)qb = pb0;
            *(uint4*)(qb + 4) = pb1;
        }
        MMA_STEP(cur, 1);
        __syncthreads();
    }
    EPILOGUE(brel, 512);
}

// ---------------- bn1d+relu, transpose back to NCHW, residual ----------------
__global__ void k_final(const float* __restrict__ x, float* __restrict__ out) {
    __shared__ float tile[32 * 257];
    int bh = blockIdx.x;
    int b = bh >> 5, h = bh & 31;
    int nb = bh * 32;
    for (int i = threadIdx.x; i < 8192; i += 256) {
        int w = i >> 8, c = i & 255;
        tile[w * 257 + c] = g_bufB[(nb + w) * NC + c];
    }
    __syncthreads();
    for (int i = threadIdx.x; i < 8192; i += 256) {
        int c = i >> 5, w = i & 31;
        float v = fmaf(tile[w * 257 + c], g_coef[512 + c], g_coef[768 + c]);
        v = fmaxf(v, 0.f);
        int o = ((b * NC + c) * 32 + h) * 32 + w;
        out[o] = v + x[o];
    }
}

extern "C" void kernel_launch(void* const* d_in, const int* in_sizes, int n_in,
                              void* d_out, int out_size) {
    const float* x      = (const float*)d_in[0];
    const void*  ei     = d_in[1];
    const float* conv_w = (const float*)d_in[2];
    const float* conv_b = (const float*)d_in[3];
    const float* bn2d_g = (const float*)d_in[4];
    const float* bn2d_b = (const float*)d_in[5];
    const float* w_rel  = (const float*)d_in[6];
    const float* b_rel  = (const float*)d_in[7];
    const float* w_root = (const float*)d_in[8];
    const float* bn1d_g = (const float*)d_in[9];
    const float* bn1d_b = (const float*)d_in[10];
    float* out = (float*)d_out;
    int E = in_sizes[1] / 2;

    k_transpose_x<<<2048, 256>>>(x);
    k_prep<<<176, 256>>>(conv_w, w_rel, w_root);
    k_detect<<<1, 256>>>((const int*)ei);
    k_conv<<<dim3(512, 2), 256>>>(conv_b);
    k_coef<<<1, 256>>>(0, bn2d_g, bn2d_b, 0);
    k_bnrelu_zero<<<4096, 256>>>();
    k_scatter<<<(E + 7) / 8, 256>>>(ei, E);
    k_cvt_agg<<<4096, 256>>>();
    k_gemm<<<dim3(512, 2), 256>>>(b_rel);
    k_coef<<<1, 256>>>(512, bn1d_g, bn1d_b, 512);
    k_final<<<2048, 256>>>(x, out);
}

// round 17
// speedup vs baseline: 1.6967x; 1.6967x over previous
#include <cuda_runtime.h>
#include <cuda_fp16.h>
#include <cstdint>

#define NNODES 65536
#define NC 256

typedef unsigned long long u64;

// Persistent scratch (no allocations allowed)
__device__ float g_bufA[NNODES * NC];       // agg (fp32 atomics, PERMUTED channel order)
__device__ float g_bufB[NNODES * NC];       // conv_out -> later g (linear channels)
__device__ uint32_t g_xh[NNODES * 128];     // xt packed half (permuted)
__device__ uint32_t g_wth[9 * 256 * 128];   // conv weights packed half [tap][co][...]
__device__ uint32_t g_nodesh[NNODES * 128]; // nodes packed half (permuted)
__device__ uint32_t g_aggh[NNODES * 128];   // agg packed half (permuted)
__device__ uint32_t g_wch[16 * 256 * 16];   // [wrel|wroot] packed half [chunk][co][...]
__device__ float g_stats[1024];
__device__ float g_coef[1024];
__device__ int   g_is32;

__device__ __forceinline__ uint32_t h2u(float x, float y) {
    __half2 h = __floats2half2_rn(x, y);
    return *(uint32_t*)&h;
}
// permuted pack of 16 consecutive channels: q[2j]={f2j,f2j+1}, q[2j+1]={f8+2j,f9+2j}
__device__ __forceinline__ void pack16(uint32_t* q, const float* f) {
    #pragma unroll
    for (int j = 0; j < 4; j++) {
        q[2 * j]     = h2u(f[2 * j], f[2 * j + 1]);
        q[2 * j + 1] = h2u(f[8 + 2 * j], f[9 + 2 * j]);
    }
}
__device__ __forceinline__ void mma16(float* c, uint2 alo, uint2 ahi, uint2 b) {
    asm volatile(
        "mma.sync.aligned.m16n8k16.row.col.f32.f16.f16.f32 "
        "{%0,%1,%2,%3}, {%4,%5,%6,%7}, {%8,%9}, {%0,%1,%2,%3};"
        : "+f"(c[0]), "+f"(c[1]), "+f"(c[2]), "+f"(c[3])
        : "r"(alo.x), "r"(ahi.x), "r"(alo.y), "r"(ahi.y), "r"(b.x), "r"(b.y));
}

// ---------------- transpose x: NCHW -> packed half node-major ----------------
__global__ void k_transpose_x(const float* __restrict__ x) {
    __shared__ float tile[256 * 33];
    int bh = blockIdx.x;
    int b = bh >> 5, h = bh & 31;
    for (int i = threadIdx.x; i < 8192; i += 256) {
        int c = i >> 5, w = i & 31;
        tile[c * 33 + w] = x[((b * NC + c) * 32 + h) * 32 + w];
    }
    __syncthreads();
    int nb = bh * 32;
    for (int i = threadIdx.x; i < 512; i += 256) {
        int w = i >> 4, g = i & 15, kc = g >> 1, hh = g & 1;
        float f[16];
        #pragma unroll
        for (int j = 0; j < 16; j++) f[j] = tile[(kc * 32 + hh * 16 + j) * 33 + w];
        uint32_t q[8];
        pack16(q, f);
        uint4* dst = (uint4*)&g_xh[(nb + w) * 128 + kc * 16 + hh * 8];
        dst[0] = ((uint4*)q)[0];
        dst[1] = ((uint4*)q)[1];
    }
}

// ---------------- weight prep: pack conv & graph weights + zero stats --------
__global__ void k_prep(const float* __restrict__ cw,
                       const float* __restrict__ wrel,
                       const float* __restrict__ wroot) {
    int i = blockIdx.x * 256 + threadIdx.x;
    if (i < 36864) {   // conv: tap(9) x co(256) x kc(8) x h(2)
        int h = i & 1, kc = (i >> 1) & 7, co = (i >> 4) & 255, tap = i >> 12;
        float f[16];
        #pragma unroll
        for (int j = 0; j < 16; j++)
            f[j] = cw[(co * 256 + kc * 32 + h * 16 + j) * 9 + tap];
        uint32_t q[8];
        pack16(q, f);
        uint4* dst = (uint4*)&g_wth[(tap * 256 + co) * 128 + kc * 16 + h * 8];
        dst[0] = ((uint4*)q)[0];
        dst[1] = ((uint4*)q)[1];
    } else if (i < 45056) {   // graph: chunk(16) x co(256) x h(2)
        int t = i - 36864;
        int h = t & 1, co = (t >> 1) & 255, chc = t >> 9;
        const float* src = (chc < 8) ? wrel : wroot;
        float f[16];
        #pragma unroll
        for (int j = 0; j < 16; j++)
            f[j] = src[co * 256 + (chc & 7) * 32 + h * 16 + j];
        uint32_t q[8];
        pack16(q, f);
        uint4* dst = (uint4*)&g_wch[(chc * 256 + co) * 16 + h * 8];
        dst[0] = ((uint4*)q)[0];
        dst[1] = ((uint4*)q)[1];
    }
    if (blockIdx.x == 0) {
        for (int j = threadIdx.x; j < 1024; j += 256) g_stats[j] = 0.f;
    }
}

// ---------------- edge dtype detection ----------------
__global__ void k_detect(const int* __restrict__ ei32) {
    __shared__ int any;
    if (threadIdx.x == 0) any = 0;
    __syncthreads();
    int a = 0;
    for (int j = threadIdx.x; j < 8192; j += 256) a |= ei32[2 * j + 1];
    if (a) atomicOr(&any, 1);
    __syncthreads();
    if (threadIdx.x == 0) g_is32 = (any != 0) ? 1 : 0;
}

#define MMA_STEP(SBUF, S)                                                     \
    do {                                                                      \
        uint2 alo[4], ahi[4], bv[4];                                          \
        _Pragma("unroll")                                                     \
        for (int mt = 0; mt < 4; mt++) {                                      \
            int row = wm0 + mt * 16 + gA;                                     \
            alo[mt] = *(const uint2*)&As[SBUF][row * 24 + (S) * 8 + 2 * cA];  \
            ahi[mt] = *(const uint2*)&As[SBUF][(row + 8) * 24 + (S) * 8 + 2 * cA]; \
        }                                                                     \
        _Pragma("unroll")                                                     \
        for (int nt = 0; nt < 4; nt++)                                        \
            bv[nt] = *(const uint2*)&Bs[SBUF][(wn0 + nt * 8 + gA) * 24 + (S) * 8 + 2 * cA]; \
        _Pragma("unroll")                                                     \
        for (int mt = 0; mt < 4; mt++)                                        \
            _Pragma("unroll")                                                 \
            for (int nt = 0; nt < 4; nt++)                                    \
                mma16(c[mt][nt], alo[mt], ahi[mt], bv[nt]);                   \
    } while (0)

// ---------------- conv 3x3: implicit GEMM, fp16 m16n8k16 (R13 config) ------
__global__ __launch_bounds__(256, 2) void k_conv(const float* __restrict__ bias) {
    __shared__ __align__(16) uint32_t As[2][128 * 24];
    __shared__ __align__(16) uint32_t Bs[2][128 * 24];
    int tid = threadIdx.x;
    int wid = tid >> 5, lane = tid & 31;
    int mbase = blockIdx.x * 128, nbase = blockIdx.y * 128;
    int wm0 = (wid >> 2) * 64, wn0 = (wid & 3) * 32;
    int gA = lane >> 2, cA = lane & 3;
    int r = tid >> 1, h = tid & 1;
    float c[4][4][4] = {};
    uint4 z4 = make_uint4(0, 0, 0, 0);

    {
        int node = mbase + r;
        int hh = ((node >> 5) & 31) - 1, ww = (node & 31) - 1;
        bool ok = ((unsigned)hh < 32u) && ((unsigned)ww < 32u);
        const uint4* ap = (const uint4*)&g_xh[(node - 33) * 128 + h * 8];
        const uint4* bp = (const uint4*)&g_wth[(nbase + r) * 128 + h * 8];
        uint32_t* qa = &As[0][r * 24 + h * 8];
        uint32_t* qb = &Bs[0][r * 24 + h * 8];
        *(uint4*)qa = ok ? ap[0] : z4;
        *(uint4*)(qa + 4) = ok ? ap[1] : z4;
        *(uint4*)qb = bp[0];
        *(uint4*)(qb + 4) = bp[1];
    }
    __syncthreads();

    for (int ch = 0; ch < 72; ch++) {
        int cur = ch & 1, nxt = cur ^ 1;
        bool has = (ch + 1 < 72);
        uint4 pa0, pa1, pb0, pb1;
        if (has) {
            int c1 = ch + 1;
            int tap = c1 >> 3, kc = c1 & 7;
            int dy = tap / 3 - 1, dx = tap % 3 - 1;
            int node = mbase + r;
            int hh = ((node >> 5) & 31) + dy, ww = (node & 31) + dx;
            bool ok = ((unsigned)hh < 32u) && ((unsigned)ww < 32u);
            const uint4* ap = (const uint4*)&g_xh[(node + dy * 32 + dx) * 128 + kc * 16 + h * 8];
            const uint4* bp = (const uint4*)&g_wth[(tap * 256 + nbase + r) * 128 + kc * 16 + h * 8];
            pa0 = ok ? ap[0] : z4;
            pa1 = ok ? ap[1] : z4;
            pb0 = bp[0];
            pb1 = bp[1];
        }
        MMA_STEP(cur, 0);
        if (has) {
            uint32_t* qa = &As[nxt][r * 24 + h * 8];
            uint32_t* qb = &Bs[nxt][r * 24 + h * 8];
            *(uint4*)qa = pa0;
            *(uint4*)(qa + 4) = pa1;
            *(uint4*)qb = pb0;
            *(uint4*)(qb + 4) = pb1;
        }
        MMA_STEP(cur, 1);
        __syncthreads();
    }

    #pragma unroll
    for (int mt = 0; mt < 4; mt++) {
        #pragma unroll
        for (int nt = 0; nt < 4; nt++) {
            int row = mbase + wm0 + mt * 16 + gA;
            int col = nbase + wn0 + nt * 8 + 2 * cA;
            float b0 = bias[col], b1 = bias[col + 1];
            *(float2*)&g_bufB[row * NC + col] =
                make_float2(c[mt][nt][0] + b0, c[mt][nt][1] + b1);
            *(float2*)&g_bufB[(row + 8) * NC + col] =
                make_float2(c[mt][nt][2] + b0, c[mt][nt][3] + b1);
        }
    }
}

// ---------------- per-channel sum/sumsq over g_bufB ----------------
__global__ void k_stats(int so) {
    int c = threadIdx.x;
    int r0 = blockIdx.x * 64;
    float s = 0.f, ss = 0.f;
    #pragma unroll 4
    for (int r = 0; r < 64; r++) {
        float v = g_bufB[(r0 + r) * NC + c];
        s += v;
        ss += v * v;
    }
    atomicAdd(&g_stats[so + c], s);
    atomicAdd(&g_stats[so + 256 + c], ss);
}

__global__ void k_coef(int so, const float* __restrict__ gamma,
                       const float* __restrict__ beta, int co) {
    int c = threadIdx.x;
    float mean = g_stats[so + c] * (1.f / NNODES);
    float var  = g_stats[so + 256 + c] * (1.f / NNODES) - mean * mean;
    float sc = gamma[c] * rsqrtf(var + 1e-5f);
    g_coef[co + c] = sc;
    g_coef[co + 256 + c] = beta[c] - mean * sc;
}

// ---------------- bn2d+relu -> packed half nodes ; zero agg -----------------
__global__ void k_bnrelu_zero() {
    int i = blockIdx.x * 256 + threadIdx.x;   // 1048576 items
    int node = i >> 4, g = i & 15;
    int base = node * NC + g * 16;
    float f[16];
    float4 zz = make_float4(0.f, 0.f, 0.f, 0.f);
    #pragma unroll
    for (int j4 = 0; j4 < 4; j4++) {
        float4 v  = *(const float4*)&g_bufB[base + j4 * 4];
        float4 sc = *(const float4*)&g_coef[g * 16 + j4 * 4];
        float4 sh = *(const float4*)&g_coef[256 + g * 16 + j4 * 4];
        v.x = fmaxf(fmaf(v.x, sc.x, sh.x), 0.f);
        v.y = fmaxf(fmaf(v.y, sc.y, sh.y), 0.f);
        v.z = fmaxf(fmaf(v.z, sc.z, sh.z), 0.f);
        v.w = fmaxf(fmaf(v.w, sc.w, sh.w), 0.f);
        *(float4*)&g_bufA[base + j4 * 4] = zz;
        f[j4 * 4 + 0] = v.x; f[j4 * 4 + 1] = v.y;
        f[j4 * 4 + 2] = v.z; f[j4 * 4 + 3] = v.w;
    }
    uint32_t q[8];
    pack16(q, f);
    uint4* dst = (uint4*)&g_nodesh[node * 128 + g * 8];
    dst[0] = ((uint4*)q)[0];
    dst[1] = ((uint4*)q)[1];
}

// ---------------- edge scatter-add (half read, fp32 RED, permuted layout) ---
__global__ void k_scatter(const void* __restrict__ ei, int E) {
    int e = blockIdx.x * 8 + (threadIdx.x >> 5);
    if (e >= E) return;
    int lane = threadIdx.x & 31;
    int src, dst;
    if (g_is32) {
        const int* p = (const int*)ei;
        src = p[e]; dst = p[E + e];
    } else {
        const long long* p = (const long long*)ei;
        src = (int)p[e]; dst = (int)p[E + e];
    }
    uint4 v = ((const uint4*)&g_nodesh[src * 128])[lane];
    float2 f0 = __half22float2(*(__half2*)&v.x);
    float2 f1 = __half22float2(*(__half2*)&v.y);
    float2 f2 = __half22float2(*(__half2*)&v.z);
    float2 f3 = __half22float2(*(__half2*)&v.w);
    float* dp = &g_bufA[dst * NC + lane * 8];
    asm volatile("red.global.add.v4.f32 [%0], {%1,%2,%3,%4};"
                 :: "l"(dp), "f"(f0.x), "f"(f0.y), "f"(f1.x), "f"(f1.y) : "memory");
    asm volatile("red.global.add.v4.f32 [%0], {%1,%2,%3,%4};"
                 :: "l"(dp + 4), "f"(f2.x), "f"(f2.y), "f"(f3.x), "f"(f3.y) : "memory");
}

// ---------------- pack agg (already permuted) fp32 -> half ------------------
__global__ void k_cvt_agg() {
    int i = blockIdx.x * 256 + threadIdx.x;
    int node = i >> 4, g = i & 15;
    const float* f = &g_bufA[node * NC + g * 16];
    uint32_t q[8];
    #pragma unroll
    for (int j = 0; j < 8; j++) q[j] = h2u(f[2 * j], f[2 * j + 1]);
    uint4* dst = (uint4*)&g_aggh[node * 128 + g * 8];
    dst[0] = ((uint4*)q)[0];
    dst[1] = ((uint4*)q)[1];
}

// ---------------- graph GEMM (R13 config) -----------------------------------
__global__ __launch_bounds__(256, 2) void k_gemm(const float* __restrict__ brel) {
    __shared__ __align__(16) uint32_t As[2][128 * 24];
    __shared__ __align__(16) uint32_t Bs[2][128 * 24];
    int tid = threadIdx.x;
    int wid = tid >> 5, lane = tid & 31;
    int mbase = blockIdx.x * 128, nbase = blockIdx.y * 128;
    int wm0 = (wid >> 2) * 64, wn0 = (wid & 3) * 32;
    int gA = lane >> 2, cA = lane & 3;
    int r = tid >> 1, h = tid & 1;
    float c[4][4][4] = {};

    {
        const uint4* ap = (const uint4*)&g_aggh[(mbase + r) * 128 + h * 8];
        const uint4* bp = (const uint4*)&g_wch[(nbase + r) * 16 + h * 8];
        uint32_t* qa = &As[0][r * 24 + h * 8];
        uint32_t* qb = &Bs[0][r * 24 + h * 8];
        *(uint4*)qa = ap[0];
        *(uint4*)(qa + 4) = ap[1];
        *(uint4*)qb = bp[0];
        *(uint4*)(qb + 4) = bp[1];
    }
    __syncthreads();

    for (int ch = 0; ch < 16; ch++) {
        int cur = ch & 1, nxt = cur ^ 1;
        bool has = (ch + 1 < 16);
        uint4 pa0, pa1, pb0, pb1;
        if (has) {
            int c1 = ch + 1;
            const uint32_t* ab = (c1 < 8) ? g_aggh : g_nodesh;
            int kc = c1 & 7;
            const uint4* ap = (const uint4*)&ab[(mbase + r) * 128 + kc * 16 + h * 8];
            const uint4* bp = (const uint4*)&g_wch[(c1 * 256 + nbase + r) * 16 + h * 8];
            pa0 = ap[0]; pa1 = ap[1];
            pb0 = bp[0]; pb1 = bp[1];
        }
        MMA_STEP(cur, 0);
        if (has) {
            uint32_t* qa = &As[nxt][r * 24 + h * 8];
            uint32_t* qb = &Bs[nxt][r * 24 + h * 8];
            *(uint4*)qa = pa0;
            *(uint4*)(qa + 4) = pa1;
            *(uint4*)qb = pb0;
            *(uint4*)(qb + 4) = pb1;
        }
        MMA_STEP(cur, 1);
        __syncthreads();
    }

    #pragma unroll
    for (int mt = 0; mt < 4; mt++) {
        #pragma unroll
        for (int nt = 0; nt < 4; nt++) {
            int row = mbase + wm0 + mt * 16 + gA;
            int col = nbase + wn0 + nt * 8 + 2 * cA;
            float b0 = brel[col], b1 = brel[col + 1];
            *(float2*)&g_bufB[row * NC + col] =
                make_float2(c[mt][nt][0] + b0, c[mt][nt][1] + b1);
            *(float2*)&g_bufB[(row + 8) * NC + col] =
                make_float2(c[mt][nt][2] + b0, c[mt][nt][3] + b1);
        }
    }
}

// ---------------- bn1d+relu, transpose back to NCHW, residual ----------------
__global__ void k_final(const float* __restrict__ x, float* __restrict__ out) {
    __shared__ float tile[32 * 257];
    int bh = blockIdx.x;
    int b = bh >> 5, h = bh & 31;
    int nb = bh * 32;
    for (int i = threadIdx.x; i < 8192; i += 256) {
        int w = i >> 8, c = i & 255;
        tile[w * 257 + c] = g_bufB[(nb + w) * NC + c];
    }
    __syncthreads();
    for (int i = threadIdx.x; i < 8192; i += 256) {
        int c = i >> 5, w = i & 31;
        float v = fmaf(tile[w * 257 + c], g_coef[512 + c], g_coef[768 + c]);
        v = fmaxf(v, 0.f);
        int o = ((b * NC + c) * 32 + h) * 32 + w;
        out[o] = v + x[o];
    }
}

extern "C" void kernel_launch(void* const* d_in, const int* in_sizes, int n_in,
                              void* d_out, int out_size) {
    const float* x      = (const float*)d_in[0];
    const void*  ei     = d_in[1];
    const float* conv_w = (const float*)d_in[2];
    const float* conv_b = (const float*)d_in[3];
    const float* bn2d_g = (const float*)d_in[4];
    const float* bn2d_b = (const float*)d_in[5];
    const float* w_rel  = (const float*)d_in[6];
    const float* b_rel  = (const float*)d_in[7];
    const float* w_root = (const float*)d_in[8];
    const float* bn1d_g = (const float*)d_in[9];
    const float* bn1d_b = (const float*)d_in[10];
    float* out = (float*)d_out;
    int E = in_sizes[1] / 2;

    k_transpose_x<<<2048, 256>>>(x);
    k_prep<<<176, 256>>>(conv_w, w_rel, w_root);
    k_detect<<<1, 256>>>((const int*)ei);
    k_conv<<<dim3(512, 2), 256>>>(conv_b);
    k_stats<<<1024, 256>>>(0);
    k_coef<<<1, 256>>>(0, bn2d_g, bn2d_b, 0);
    k_bnrelu_zero<<<4096, 256>>>();
    k_scatter<<<(E + 7) / 8, 256>>>(ei, E);
    k_cvt_agg<<<4096, 256>>>();
    k_gemm<<<dim3(512, 2), 256>>>(b_rel);
    k_stats<<<1024, 256>>>(512);
    k_coef<<<1, 256>>>(512, bn1d_g, bn1d_b, 512);
    k_final<<<2048, 256>>>(x, out);
}